// round 10
// baseline (speedup 1.0000x reference)
#include <cuda_runtime.h>
#include <math.h>

#define B_  64
#define T_  512
#define D_  512
#define H_  1024
#define G4  4096
#define M1  32768          // B_*T_
#define NBLK 128
#define RTH 256

// Recurrence smem: Bs[32][1028] + As2[2][64][68]
#define BS_P 1028
#define AS_W 68
#define R_SMEM_BYTES ((32 * BS_P + 2 * 64 * AS_W) * 4)    // 166400

// Phase-1 smem: As[2][128][36] + Bs[2][64][36]
#define P1_AW 36
#define P1_SMEM_BYTES ((2 * 128 * P1_AW + 2 * 64 * P1_AW) * 4)  // 55296

typedef unsigned long long u64;

// ---------------------------------------------------------------------------
// Device globals (allocation-free scratch)
// ---------------------------------------------------------------------------
__device__ float g_xg[(size_t)M1 * G4];    // xg = x@Wx + b   (512 MB)
__device__ float g_hb[2][B_ * H_];         // double-buffered hidden state
__device__ unsigned g_cnt;                 // grid barrier counter
__device__ unsigned g_gen;                 // grid barrier generation

// ---------------------------------------------------------------------------
// f32x2 helpers
// ---------------------------------------------------------------------------
__device__ __forceinline__ void fma2(u64& d, u64 a, u64 b) {
    asm("fma.rn.f32x2 %0, %1, %2, %0;" : "+l"(d) : "l"(a), "l"(b));
}
__device__ __forceinline__ float red2(u64 v) {
    float lo, hi;
    asm("mov.b64 {%0, %1}, %2;" : "=f"(lo), "=f"(hi) : "l"(v));
    return lo + hi;
}

// ---------------------------------------------------------------------------
// Phase 1: xg[M1, G4] = x[M1, D] @ Wx[D, G4] + bias
// Block tile 128(M) x 64(N), 256 threads, K-pair packed f32x2.
// Lane tile: 4 rows x 8 cols (rows w*16+rl+4i, cols ncol0+8j+cl).
// ---------------------------------------------------------------------------
__global__ void __launch_bounds__(256, 2)
gemm_xw(const float* __restrict__ x,
        const float* __restrict__ Wx,
        const float* __restrict__ bias) {
    extern __shared__ float sm[];
    float* As = sm;                       // [2][128][36]
    float* Bs = sm + 2 * 128 * P1_AW;     // [2][64][36]

    const int bm = blockIdx.y;
    const int bn = blockIdx.x;
    const int tid = threadIdx.x;
    const int w  = tid >> 5;
    const int l  = tid & 31;
    const int rl = l >> 3;     // 0..3
    const int cl = l & 7;      // 0..7
    const int ncol0 = bn * 64;

    // A staging: row = tid>>1 (0..127), kq = (tid&1)*16
    const int s_arow = tid >> 1;
    const int s_akq  = (tid & 1) * 16;
    const float* axp = x + (size_t)(bm * 128 + s_arow) * D_ + s_akq;

    // B staging: kr = tid>>3 (0..31), cgrp = (tid&7)*8
    const int s_bkr = tid >> 3;
    const int s_bc  = (tid & 7) * 8;
    const float* bxp = Wx + (size_t)s_bkr * G4 + ncol0 + s_bc;

    int aoff[4], boff[8];
#pragma unroll
    for (int i = 0; i < 4; ++i) aoff[i] = (w * 16 + rl + 4 * i) * P1_AW;
#pragma unroll
    for (int j = 0; j < 8; ++j) boff[j] = (8 * j + cl) * P1_AW;

    u64 acc[4][8];
#pragma unroll
    for (int i = 0; i < 4; ++i)
#pragma unroll
        for (int j = 0; j < 8; ++j) acc[i][j] = 0ull;

    // prologue: load + stage chunk 0
    float4 av0 = *(const float4*)(axp);
    float4 av1 = *(const float4*)(axp + 4);
    float4 av2 = *(const float4*)(axp + 8);
    float4 av3 = *(const float4*)(axp + 12);
    float4 bw0 = *(const float4*)(bxp);
    float4 bw1 = *(const float4*)(bxp + 4);
    {
        float* Ad = As;
        float* Bd = Bs;
        *(float4*)&Ad[s_arow * P1_AW + s_akq + 0]  = av0;
        *(float4*)&Ad[s_arow * P1_AW + s_akq + 4]  = av1;
        *(float4*)&Ad[s_arow * P1_AW + s_akq + 8]  = av2;
        *(float4*)&Ad[s_arow * P1_AW + s_akq + 12] = av3;
        Bd[(s_bc + 0) * P1_AW + s_bkr] = bw0.x;
        Bd[(s_bc + 1) * P1_AW + s_bkr] = bw0.y;
        Bd[(s_bc + 2) * P1_AW + s_bkr] = bw0.z;
        Bd[(s_bc + 3) * P1_AW + s_bkr] = bw0.w;
        Bd[(s_bc + 4) * P1_AW + s_bkr] = bw1.x;
        Bd[(s_bc + 5) * P1_AW + s_bkr] = bw1.y;
        Bd[(s_bc + 6) * P1_AW + s_bkr] = bw1.z;
        Bd[(s_bc + 7) * P1_AW + s_bkr] = bw1.w;
    }
    __syncthreads();

#pragma unroll 1
    for (int kc = 0; kc < 16; ++kc) {
        if (kc < 15) {
            const float* ap = axp + (kc + 1) * 32;
            const float* bp = bxp + (size_t)(kc + 1) * 32 * G4;
            av0 = *(const float4*)(ap);
            av1 = *(const float4*)(ap + 4);
            av2 = *(const float4*)(ap + 8);
            av3 = *(const float4*)(ap + 12);
            bw0 = *(const float4*)(bp);
            bw1 = *(const float4*)(bp + 4);
        }
        const float* A  = As + (kc & 1) * (128 * P1_AW);
        const float* Bb = Bs + (kc & 1) * (64 * P1_AW);
#pragma unroll
        for (int kk = 0; kk < 32; kk += 4) {
            ulonglong2 a0 = *(const ulonglong2*)(A + aoff[0] + kk);
            ulonglong2 a1 = *(const ulonglong2*)(A + aoff[1] + kk);
            ulonglong2 a2 = *(const ulonglong2*)(A + aoff[2] + kk);
            ulonglong2 a3 = *(const ulonglong2*)(A + aoff[3] + kk);
#pragma unroll
            for (int jh = 0; jh < 2; ++jh) {
                ulonglong2 b0 = *(const ulonglong2*)(Bb + boff[jh * 4 + 0] + kk);
                ulonglong2 b1 = *(const ulonglong2*)(Bb + boff[jh * 4 + 1] + kk);
                ulonglong2 b2 = *(const ulonglong2*)(Bb + boff[jh * 4 + 2] + kk);
                ulonglong2 b3 = *(const ulonglong2*)(Bb + boff[jh * 4 + 3] + kk);
                fma2(acc[0][jh*4+0], a0.x, b0.x); fma2(acc[0][jh*4+1], a0.x, b1.x);
                fma2(acc[0][jh*4+2], a0.x, b2.x); fma2(acc[0][jh*4+3], a0.x, b3.x);
                fma2(acc[1][jh*4+0], a1.x, b0.x); fma2(acc[1][jh*4+1], a1.x, b1.x);
                fma2(acc[1][jh*4+2], a1.x, b2.x); fma2(acc[1][jh*4+3], a1.x, b3.x);
                fma2(acc[2][jh*4+0], a2.x, b0.x); fma2(acc[2][jh*4+1], a2.x, b1.x);
                fma2(acc[2][jh*4+2], a2.x, b2.x); fma2(acc[2][jh*4+3], a2.x, b3.x);
                fma2(acc[3][jh*4+0], a3.x, b0.x); fma2(acc[3][jh*4+1], a3.x, b1.x);
                fma2(acc[3][jh*4+2], a3.x, b2.x); fma2(acc[3][jh*4+3], a3.x, b3.x);
                fma2(acc[0][jh*4+0], a0.y, b0.y); fma2(acc[0][jh*4+1], a0.y, b1.y);
                fma2(acc[0][jh*4+2], a0.y, b2.y); fma2(acc[0][jh*4+3], a0.y, b3.y);
                fma2(acc[1][jh*4+0], a1.y, b0.y); fma2(acc[1][jh*4+1], a1.y, b1.y);
                fma2(acc[1][jh*4+2], a1.y, b2.y); fma2(acc[1][jh*4+3], a1.y, b3.y);
                fma2(acc[2][jh*4+0], a2.y, b0.y); fma2(acc[2][jh*4+1], a2.y, b1.y);
                fma2(acc[2][jh*4+2], a2.y, b2.y); fma2(acc[2][jh*4+3], a2.y, b3.y);
                fma2(acc[3][jh*4+0], a3.y, b0.y); fma2(acc[3][jh*4+1], a3.y, b1.y);
                fma2(acc[3][jh*4+2], a3.y, b2.y); fma2(acc[3][jh*4+3], a3.y, b3.y);
            }
        }
        if (kc < 15) {
            float* Ad = As + ((kc + 1) & 1) * (128 * P1_AW);
            float* Bd = Bs + ((kc + 1) & 1) * (64 * P1_AW);
            *(float4*)&Ad[s_arow * P1_AW + s_akq + 0]  = av0;
            *(float4*)&Ad[s_arow * P1_AW + s_akq + 4]  = av1;
            *(float4*)&Ad[s_arow * P1_AW + s_akq + 8]  = av2;
            *(float4*)&Ad[s_arow * P1_AW + s_akq + 12] = av3;
            Bd[(s_bc + 0) * P1_AW + s_bkr] = bw0.x;
            Bd[(s_bc + 1) * P1_AW + s_bkr] = bw0.y;
            Bd[(s_bc + 2) * P1_AW + s_bkr] = bw0.z;
            Bd[(s_bc + 3) * P1_AW + s_bkr] = bw0.w;
            Bd[(s_bc + 4) * P1_AW + s_bkr] = bw1.x;
            Bd[(s_bc + 5) * P1_AW + s_bkr] = bw1.y;
            Bd[(s_bc + 6) * P1_AW + s_bkr] = bw1.z;
            Bd[(s_bc + 7) * P1_AW + s_bkr] = bw1.w;
        }
        __syncthreads();
    }

    // Epilogue: reduce k-pairs, add bias, store
    float bb[8];
#pragma unroll
    for (int j = 0; j < 8; ++j) bb[j] = bias[ncol0 + 8 * j + cl];
#pragma unroll
    for (int i = 0; i < 4; ++i) {
        size_t row = (size_t)(bm * 128 + w * 16 + rl + 4 * i);
        float* crow = g_xg + row * G4 + ncol0 + cl;
#pragma unroll
        for (int j = 0; j < 8; ++j)
            crow[8 * j] = red2(acc[i][j]) + bb[j];
    }
}

// ---------------------------------------------------------------------------
// Init: zero h buffer 0 and barrier counter
// ---------------------------------------------------------------------------
__global__ void init_state() {
    int idx = blockIdx.x * blockDim.x + threadIdx.x;
    g_hb[0][idx] = 0.0f;
    if (idx == 0) g_cnt = 0u;
}

// ---------------------------------------------------------------------------
// Grid-wide barrier (all NBLK blocks resident)
// ---------------------------------------------------------------------------
__device__ __forceinline__ void grid_barrier() {
    __threadfence();
    __syncthreads();
    if (threadIdx.x == 0) {
        volatile unsigned* vg = &g_gen;
        unsigned gen = *vg;
        if (atomicAdd(&g_cnt, 1u) == NBLK - 1) {
            atomicExch(&g_cnt, 0u);
            __threadfence();
            atomicAdd((unsigned*)&g_gen, 1u);
        } else {
            while (*vg == gen) { }
        }
    }
    __syncthreads();
}

// ---------------------------------------------------------------------------
// Persistent recurrence. Block owns 8 hidden cols (32 gate-cols).
// Bs[g*8+jj][k] (K-major per col, padded 1028) resident all 512 steps.
// Lane tile: rows {w*8+rl, w*8+rl+4} x all 4 gates of hidden col j0+cl.
// K-pair packed: acc u64 += (h_k,h_k+1)*(W_k,W_k+1); reduce at step end.
// Per 4k: 6 LDS.128 + 16 fma2 (FMA-bound @16 cyc/k/SMSP).
// ---------------------------------------------------------------------------
__global__ void __launch_bounds__(RTH, 1)
lstm_persist(const float* __restrict__ Wh, float* __restrict__ out) {
    extern __shared__ float sm[];
    float* Bs  = sm;                      // [32][1028]
    float* As2 = sm + 32 * BS_P;          // [2][64][68]

    const int tid = threadIdx.x;
    const int w  = tid >> 5;
    const int l  = tid & 31;
    const int rl = l >> 3;      // 0..3
    const int cl = l & 7;       // 0..7
    const int j0 = blockIdx.x * 8;

    // One-time Wh slice load: Bs[(g*8+jj)][k] = Wh[k][g*H + j0 + jj]
    for (int idx = tid; idx < 32 * 1024; idx += RTH) {
        int c = idx >> 10, k = idx & 1023;
        Bs[c * BS_P + k] = Wh[(size_t)k * G4 + (c >> 3) * H_ + j0 + (c & 7)];
    }

    const int aoff0 = (w * 8 + rl) * AS_W;
    const int aoff1 = aoff0 + 4 * AS_W;
    const float* bp0 = Bs + (0 * 8 + cl) * BS_P;
    const float* bp1 = Bs + (1 * 8 + cl) * BS_P;
    const float* bp2 = Bs + (2 * 8 + cl) * BS_P;
    const float* bp3 = Bs + (3 * 8 + cl) * BS_P;

    // staging: srow = tid&63, sq = tid>>6 (16 floats per thread per 64k chunk)
    const int srow = tid & 63;
    const int sq   = tid >> 6;
    const int soff = srow * AS_W + sq * 16;

    const int r0 = w * 8 + rl;
    const int r1 = r0 + 4;
    const int j  = j0 + cl;

    float cc0 = 0.f, cc1 = 0.f;
    __syncthreads();

    for (int t = 0; t < T_; ++t) {
        const float* hin  = g_hb[t & 1];
        float*       hout = g_hb[(t + 1) & 1];

        // prefetch xg gates for the epilogue (streaming)
        const float* xb0 = g_xg + ((size_t)r0 * T_ + t) * G4 + j;
        const float* xb1 = g_xg + ((size_t)r1 * T_ + t) * G4 + j;
        float xi0 = __ldcs(xb0);           float xi1 = __ldcs(xb1);
        float xf0 = __ldcs(xb0 + H_);      float xf1 = __ldcs(xb1 + H_);
        float xg0 = __ldcs(xb0 + 2 * H_);  float xg1 = __ldcs(xb1 + 2 * H_);
        float xo0 = __ldcs(xb0 + 3 * H_);  float xo1 = __ldcs(xb1 + 3 * H_);

        u64 a00 = 0, a01 = 0, a02 = 0, a03 = 0;   // row r0, gates i f g o
        u64 a10 = 0, a11 = 0, a12 = 0, a13 = 0;   // row r1

        // stage chunk 0
        {
            const float* hp = hin + srow * H_ + sq * 16;
            float4 p0 = __ldcg((const float4*)(hp));
            float4 p1 = __ldcg((const float4*)(hp + 4));
            float4 p2 = __ldcg((const float4*)(hp + 8));
            float4 p3 = __ldcg((const float4*)(hp + 12));
            *(float4*)&As2[soff + 0]  = p0;
            *(float4*)&As2[soff + 4]  = p1;
            *(float4*)&As2[soff + 8]  = p2;
            *(float4*)&As2[soff + 12] = p3;
        }
        __syncthreads();

#pragma unroll 1
        for (int kc = 0; kc < 16; ++kc) {
            float4 q0, q1, q2, q3;
            if (kc < 15) {
                const float* hp = hin + srow * H_ + (kc + 1) * 64 + sq * 16;
                q0 = __ldcg((const float4*)(hp));
                q1 = __ldcg((const float4*)(hp + 4));
                q2 = __ldcg((const float4*)(hp + 8));
                q3 = __ldcg((const float4*)(hp + 12));
            }
            const float* A = As2 + (kc & 1) * (64 * AS_W);
            const int kg = kc * 64;
#pragma unroll
            for (int kk = 0; kk < 64; kk += 4) {
                ulonglong2 av0 = *(const ulonglong2*)(A + aoff0 + kk);
                ulonglong2 av1 = *(const ulonglong2*)(A + aoff1 + kk);
                ulonglong2 b0  = *(const ulonglong2*)(bp0 + kg + kk);
                ulonglong2 b1  = *(const ulonglong2*)(bp1 + kg + kk);
                ulonglong2 b2  = *(const ulonglong2*)(bp2 + kg + kk);
                ulonglong2 b3  = *(const ulonglong2*)(bp3 + kg + kk);
                fma2(a00, av0.x, b0.x); fma2(a01, av0.x, b1.x);
                fma2(a02, av0.x, b2.x); fma2(a03, av0.x, b3.x);
                fma2(a10, av1.x, b0.x); fma2(a11, av1.x, b1.x);
                fma2(a12, av1.x, b2.x); fma2(a13, av1.x, b3.x);
                fma2(a00, av0.y, b0.y); fma2(a01, av0.y, b1.y);
                fma2(a02, av0.y, b2.y); fma2(a03, av0.y, b3.y);
                fma2(a10, av1.y, b0.y); fma2(a11, av1.y, b1.y);
                fma2(a12, av1.y, b2.y); fma2(a13, av1.y, b3.y);
            }
            if (kc < 15) {
                float* Ad = As2 + ((kc + 1) & 1) * (64 * AS_W);
                *(float4*)&Ad[soff + 0]  = q0;
                *(float4*)&Ad[soff + 4]  = q1;
                *(float4*)&Ad[soff + 8]  = q2;
                *(float4*)&Ad[soff + 12] = q3;
            }
            __syncthreads();
        }

        // Pointwise cells (2 per lane, fully local)
        {
            float vi = red2(a00) + xi0;
            float vf = red2(a01) + xf0;
            float vg = red2(a02) + xg0;
            float vo = red2(a03) + xo0;
            float si = 1.0f / (1.0f + expf(-vi));
            float sf = 1.0f / (1.0f + expf(-vf));
            float tg = tanhf(vg);
            float so = 1.0f / (1.0f + expf(-vo));
            float c = sf * cc0 + si * tg;
            cc0 = c;
            float h = so * tanhf(c);
            hout[r0 * H_ + j] = h;
            out[((size_t)r0 * T_ + t) * H_ + j] = h;
        }
        {
            float vi = red2(a10) + xi1;
            float vf = red2(a11) + xf1;
            float vg = red2(a12) + xg1;
            float vo = red2(a13) + xo1;
            float si = 1.0f / (1.0f + expf(-vi));
            float sf = 1.0f / (1.0f + expf(-vf));
            float tg = tanhf(vg);
            float so = 1.0f / (1.0f + expf(-vo));
            float c = sf * cc1 + si * tg;
            cc1 = c;
            float h = so * tanhf(c);
            hout[r1 * H_ + j] = h;
            out[((size_t)r1 * T_ + t) * H_ + j] = h;
        }

        if (t < T_ - 1) grid_barrier();
    }
}

// ---------------------------------------------------------------------------
// Launch: 3 graph nodes
// ---------------------------------------------------------------------------
extern "C" void kernel_launch(void* const* d_in, const int* in_sizes, int n_in,
                              void* d_out, int out_size) {
    const float* x    = (const float*)d_in[0];   // [B, T, D]
    const float* Wx   = (const float*)d_in[1];   // [D, 4H]
    const float* Wh   = (const float*)d_in[2];   // [H, 4H]
    const float* bias = (const float*)d_in[3];   // [4H]
    float* out = (float*)d_out;                  // [B, T, H]

    cudaFuncSetAttribute(lstm_persist,
                         cudaFuncAttributeMaxDynamicSharedMemorySize, R_SMEM_BYTES);
    cudaFuncSetAttribute(gemm_xw,
                         cudaFuncAttributeMaxDynamicSharedMemorySize, P1_SMEM_BYTES);

    dim3 g1(G4 / 64, M1 / 128);                  // (64, 256)
    gemm_xw<<<g1, 256, P1_SMEM_BYTES>>>(x, Wx, bias);
    init_state<<<256, 256>>>();
    lstm_persist<<<NBLK, RTH, R_SMEM_BYTES>>>(Wh, out);
}

// round 12
// speedup vs baseline: 2.5976x; 2.5976x over previous
#include <cuda_runtime.h>
#include <cuda_bf16.h>
#include <math.h>

typedef unsigned int u32;
typedef unsigned long long u64;

#define B_  64
#define T_  512
#define D_  512
#define H_  1024
#define G4  4096
#define M1  32768          // B_*T_
#define NBLK 128
#define RTH 256

// ---- lstm_persist smem layout (bytes) ----
#define A_STRIDE_B 2064                 // 1032 bf16 per row (16B-offset swizzle-free pad)
#define SM_AHI 0
#define SM_ALO (32 * A_STRIDE_B)        // 66048
#define SM_B   (2 * 32 * A_STRIDE_B)    // 132096
#define B_STRIDE_B 272                  // 136 bf16 per row
#define B_LO_OFF 17408                  // 64 * 272
#define BST 34816                       // per stage (hi + lo)
#define SM_DX (SM_B + 2 * BST)          // 201728
#define DX_S 66
#define SMEM_TOTAL (SM_DX + 32 * DX_S * 4)   // 210176

// ---------------------------------------------------------------------------
// Device globals (allocation-free scratch)
// ---------------------------------------------------------------------------
__device__ float g_xg[(size_t)M1 * G4];              // xg = x@Wx + b (512 MB)
__device__ __nv_bfloat16 g_wthi[(size_t)G4 * H_];    // Wh^T hi, [m_global][k]
__device__ __nv_bfloat16 g_wtlo[(size_t)G4 * H_];    // Wh^T lo
__device__ __nv_bfloat16 g_hh[2][B_ * H_];           // h hi, [b][k], double-buffered
__device__ __nv_bfloat16 g_hl[2][B_ * H_];           // h lo
__device__ unsigned g_cnt;
__device__ unsigned g_gen;

// ---------------------------------------------------------------------------
// helpers
// ---------------------------------------------------------------------------
__device__ __forceinline__ u32 smem_u32(const void* p) {
    u32 a;
    asm("{ .reg .u64 t; cvta.to.shared.u64 t, %1; cvt.u32.u64 %0, t; }"
        : "=r"(a) : "l"(p));
    return a;
}

__device__ __forceinline__ void ldsm4(u32* r, u32 addr) {
    asm volatile("ldmatrix.sync.aligned.m8n8.x4.shared.b16 {%0,%1,%2,%3}, [%4];"
                 : "=r"(r[0]), "=r"(r[1]), "=r"(r[2]), "=r"(r[3]) : "r"(addr));
}

__device__ __forceinline__ void mma_bf16(float* d, const u32* a, u32 b0, u32 b1) {
    asm volatile(
        "mma.sync.aligned.m16n8k16.row.col.f32.bf16.bf16.f32 "
        "{%0,%1,%2,%3}, {%4,%5,%6,%7}, {%8,%9}, {%0,%1,%2,%3};"
        : "+f"(d[0]), "+f"(d[1]), "+f"(d[2]), "+f"(d[3])
        : "r"(a[0]), "r"(a[1]), "r"(a[2]), "r"(a[3]), "r"(b0), "r"(b1));
}

// ---------------------------------------------------------------------------
// Phase 1 (R1 version, best measured): xg = x@Wx + bias. 128x128 tile, BK=8.
// ---------------------------------------------------------------------------
__global__ __launch_bounds__(256) void gemm_xw(const float* __restrict__ x,
                                               const float* __restrict__ Wx,
                                               const float* __restrict__ bias) {
    __shared__ float As[8][128];
    __shared__ float Bs[8][128];

    const int bm = blockIdx.y, bn = blockIdx.x;
    const int tid = threadIdx.x;
    const int tx = tid & 15, ty = tid >> 4;

    float acc[8][8];
#pragma unroll
    for (int i = 0; i < 8; ++i)
#pragma unroll
        for (int j = 0; j < 8; ++j) acc[i][j] = 0.0f;

    const int a_lrow = tid >> 1;
    const int a_kc   = (tid & 1) * 4;
    const float* Aptr = x + (size_t)(bm * 128 + a_lrow) * D_;
    const int b_lrow = tid >> 5;
    const int b_lcol = (tid & 31) * 4;
    const int ncol0 = bn * 128;

    for (int k0 = 0; k0 < D_; k0 += 8) {
        float4 av = *(const float4*)(Aptr + k0 + a_kc);
        float4 bv = *(const float4*)(Wx + (size_t)(k0 + b_lrow) * G4 + ncol0 + b_lcol);
        As[a_kc + 0][a_lrow] = av.x;
        As[a_kc + 1][a_lrow] = av.y;
        As[a_kc + 2][a_lrow] = av.z;
        As[a_kc + 3][a_lrow] = av.w;
        *(float4*)&Bs[b_lrow][b_lcol] = bv;
        __syncthreads();
#pragma unroll
        for (int k = 0; k < 8; ++k) {
            float a[8], b[8];
            *(float4*)(a)     = *(float4*)&As[k][ty * 8];
            *(float4*)(a + 4) = *(float4*)&As[k][ty * 8 + 4];
            *(float4*)(b)     = *(float4*)&Bs[k][tx * 8];
            *(float4*)(b + 4) = *(float4*)&Bs[k][tx * 8 + 4];
#pragma unroll
            for (int i = 0; i < 8; ++i)
#pragma unroll
                for (int j = 0; j < 8; ++j) acc[i][j] = fmaf(a[i], b[j], acc[i][j]);
        }
        __syncthreads();
    }

    float bb[8];
#pragma unroll
    for (int j = 0; j < 8; ++j) bb[j] = bias[ncol0 + tx * 8 + j];
#pragma unroll
    for (int i = 0; i < 8; ++i) {
        size_t row = (size_t)(bm * 128 + ty * 8 + i);
        float* crow = g_xg + row * G4 + ncol0 + tx * 8;
        *(float4*)(crow)     = make_float4(acc[i][0] + bb[0], acc[i][1] + bb[1],
                                           acc[i][2] + bb[2], acc[i][3] + bb[3]);
        *(float4*)(crow + 4) = make_float4(acc[i][4] + bb[4], acc[i][5] + bb[5],
                                           acc[i][6] + bb[6], acc[i][7] + bb[7]);
    }
}

// ---------------------------------------------------------------------------
// Wh -> WhT bf16 hi/lo. m_global = bx*32 + jj*4 + g  for gate-col
// c = g*1024 + bx*8 + jj   (bx = block, jj = hidden col within block).
// ---------------------------------------------------------------------------
__global__ void prep_whT(const float* __restrict__ Wh) {
    __shared__ float ts[32][33];
    const int k0 = blockIdx.x * 32;
    const int c0 = blockIdx.y * 32;
    const int txl = threadIdx.x, tyl = threadIdx.y;   // (32, 8)

#pragma unroll
    for (int r = 0; r < 4; ++r) {
        int kr = tyl + 8 * r;
        ts[kr][txl] = Wh[(size_t)(k0 + kr) * G4 + c0 + txl];
    }
    __syncthreads();
#pragma unroll
    for (int r = 0; r < 4; ++r) {
        int cl = tyl + 8 * r;
        int c = c0 + cl;
        int bx = (c & 1023) >> 3;
        int g  = c >> 10;
        int jj = c & 7;
        int mg = bx * 32 + jj * 4 + g;
        float w = ts[txl][cl];
        __nv_bfloat16 hi = __float2bfloat16(w);
        float lof = w - __bfloat162float(hi);
        g_wthi[(size_t)mg * H_ + k0 + txl] = hi;
        g_wtlo[(size_t)mg * H_ + k0 + txl] = __float2bfloat16(lof);
    }
}

// ---------------------------------------------------------------------------
// Init: zero h bf16 buffers + barrier counter
// ---------------------------------------------------------------------------
__global__ void init_state() {
    int idx = blockIdx.x * blockDim.x + threadIdx.x;   // 65536
    g_hh[0][idx] = __float2bfloat16(0.0f);
    g_hl[0][idx] = __float2bfloat16(0.0f);
    if (idx == 0) g_cnt = 0u;
}

// ---------------------------------------------------------------------------
// Grid-wide barrier (NBLK blocks resident)
// ---------------------------------------------------------------------------
__device__ __forceinline__ void grid_barrier() {
    __threadfence();
    __syncthreads();
    if (threadIdx.x == 0) {
        volatile unsigned* vg = &g_gen;
        unsigned gen = *vg;
        if (atomicAdd(&g_cnt, 1u) == NBLK - 1) {
            atomicExch(&g_cnt, 0u);
            __threadfence();
            atomicAdd((unsigned*)&g_gen, 1u);
        } else {
            while (*vg == gen) { }
        }
    }
    __syncthreads();
}

// ---------------------------------------------------------------------------
// Persistent mma.sync recurrence. Block bx: M=32 gate-cols (8 hidden cols x
// 4 gates, gate-interleaved m=jj*4+g), N=64 batch, K=1024.
// WhT hi/lo resident in smem; h hi/lo streamed in 8 double-buffered chunks.
// D = WhT_hi@h_hi + WhT_lo@h_hi + WhT_hi@h_lo, fp32 register accumulators.
// ---------------------------------------------------------------------------
__global__ void __launch_bounds__(RTH, 1)
lstm_persist(float* __restrict__ out) {
    extern __shared__ char smc[];
    const u32 sb = smem_u32(smc);
    const int tid = threadIdx.x;
    const int wid = tid >> 5;
    const int lane = tid & 31;
    const int bx = blockIdx.x;
    const int m0g = bx * 32;       // global WhT row base
    const int j0 = bx * 8;         // hidden col base

    // ---- one-time resident A load: WhT hi/lo [32][1024] bf16 ----
#pragma unroll
    for (int it = 0; it < 16; ++it) {
        int cid = tid + it * RTH;            // 0..4095
        int row = cid >> 7;                  // 0..31
        int c   = cid & 127;                 // uint4 col
        size_t si = ((size_t)(m0g + row) << 10) + c * 8;
        *(uint4*)(smc + SM_AHI + row * A_STRIDE_B + c * 16) =
            __ldg((const uint4*)(g_wthi + si));
        *(uint4*)(smc + SM_ALO + row * A_STRIDE_B + c * 16) =
            __ldg((const uint4*)(g_wtlo + si));
    }

    // ---- warp tile: m-strip (16) x n-strip (16) ----
    const int wm = (wid >> 2) * 16;          // 0 or 16
    const int wn = (wid & 3) * 16;           // 0,16,32,48

    // ldmatrix lane addresses
    const u32 aAddrHi = sb + SM_AHI + (wm + (lane & 15)) * A_STRIDE_B + ((lane >> 4) << 4);
    const u32 aAddrLo = aAddrHi + (SM_ALO - SM_AHI);
    const int bn_row  = wn + ((lane >> 4) << 3) + (lane & 7);
    const u32 bLaneOff = (u32)(bn_row * B_STRIDE_B + (((lane >> 3) & 1) << 4));

    // pointwise coords: thread -> (batch pb, hidden cols pj, pj+4)
    const int pb = tid >> 2;
    const int pj = tid & 3;
    float cc0 = 0.f, cc1 = 0.f;

    __syncthreads();

    for (int t = 0; t < T_; ++t) {
        const __nv_bfloat16* hhi = g_hh[t & 1];
        const __nv_bfloat16* hlo = g_hl[t & 1];
        __nv_bfloat16* hh_nxt = g_hh[(t + 1) & 1];
        __nv_bfloat16* hl_nxt = g_hl[(t + 1) & 1];

        // prefetch xg for this thread's 2 cells (independent of h)
        float xv[8];
        {
            const float* xgb = g_xg + ((size_t)pb * T_ + t) * G4 + j0;
#pragma unroll
            for (int i = 0; i < 2; ++i) {
                int jj = pj + 4 * i;
#pragma unroll
                for (int g = 0; g < 4; ++g)
                    xv[i * 4 + g] = __ldcs(xgb + g * H_ + jj);
            }
        }

        float acc0[4] = {0.f, 0.f, 0.f, 0.f};   // cols wn..wn+7
        float acc1[4] = {0.f, 0.f, 0.f, 0.f};   // cols wn+8..wn+15

        // ---- B chunk 0: load + stage ----
        uint4 rh[4], rl[4];
        {
#pragma unroll
            for (int it = 0; it < 4; ++it) {
                int cid = tid + it * RTH;        // 0..1023
                int row = cid >> 4, c = cid & 15;
                size_t si = ((size_t)row << 10) + c * 8;
                rh[it] = __ldcg((const uint4*)(hhi + si));
                rl[it] = __ldcg((const uint4*)(hlo + si));
            }
#pragma unroll
            for (int it = 0; it < 4; ++it) {
                int cid = tid + it * RTH;
                int row = cid >> 4, c = cid & 15;
                *(uint4*)(smc + SM_B + row * B_STRIDE_B + c * 16) = rh[it];
                *(uint4*)(smc + SM_B + B_LO_OFF + row * B_STRIDE_B + c * 16) = rl[it];
            }
        }
        __syncthreads();

#pragma unroll 1
        for (int kc = 0; kc < 8; ++kc) {
            if (kc < 7) {
#pragma unroll
                for (int it = 0; it < 4; ++it) {
                    int cid = tid + it * RTH;
                    int row = cid >> 4, c = cid & 15;
                    size_t si = ((size_t)row << 10) + (kc + 1) * 128 + c * 8;
                    rh[it] = __ldcg((const uint4*)(hhi + si));
                    rl[it] = __ldcg((const uint4*)(hlo + si));
                }
            }
            const u32 bbase = sb + SM_B + (u32)(kc & 1) * BST + bLaneOff;
            const u32 abase = (u32)(kc * 256);   // 128 bf16 = 256 B per chunk
#pragma unroll
            for (int kt = 0; kt < 8; ++kt) {
                u32 ahi[4], alo[4], bhi[4], blo[4];
                ldsm4(ahi, aAddrHi + abase + kt * 32);
                ldsm4(alo, aAddrLo + abase + kt * 32);
                ldsm4(bhi, bbase + kt * 32);
                ldsm4(blo, bbase + B_LO_OFF + kt * 32);
                mma_bf16(acc0, ahi, bhi[0], bhi[1]);
                mma_bf16(acc1, ahi, bhi[2], bhi[3]);
                mma_bf16(acc0, alo, bhi[0], bhi[1]);
                mma_bf16(acc1, alo, bhi[2], bhi[3]);
                mma_bf16(acc0, ahi, blo[0], blo[1]);
                mma_bf16(acc1, ahi, blo[2], blo[3]);
            }
            if (kc < 7) {
                const u32 dst = SM_B + (u32)((kc + 1) & 1) * BST;
#pragma unroll
                for (int it = 0; it < 4; ++it) {
                    int cid = tid + it * RTH;
                    int row = cid >> 4, c = cid & 15;
                    *(uint4*)(smc + dst + row * B_STRIDE_B + c * 16) = rh[it];
                    *(uint4*)(smc + dst + B_LO_OFF + row * B_STRIDE_B + c * 16) = rl[it];
                }
            }
            __syncthreads();
        }

        // ---- write D fragments to smem Dx[32 m][66] ----
        {
            float* dx = (float*)(smc + SM_DX);
            int r0 = wm + (lane >> 2);
            int col = wn + 2 * (lane & 3);
            dx[r0 * DX_S + col]           = acc0[0];
            dx[r0 * DX_S + col + 1]       = acc0[1];
            dx[(r0 + 8) * DX_S + col]     = acc0[2];
            dx[(r0 + 8) * DX_S + col + 1] = acc0[3];
            dx[r0 * DX_S + col + 8]       = acc1[0];
            dx[r0 * DX_S + col + 9]       = acc1[1];
            dx[(r0 + 8) * DX_S + col + 8] = acc1[2];
            dx[(r0 + 8) * DX_S + col + 9] = acc1[3];
        }
        __syncthreads();

        // ---- pointwise: 2 cells per thread ----
        {
            const float* dx = (const float*)(smc + SM_DX);
#pragma unroll
            for (int i = 0; i < 2; ++i) {
                int jj = pj + 4 * i;
                int m = jj << 2;
                float vi = dx[(m + 0) * DX_S + pb] + xv[i * 4 + 0];
                float vf = dx[(m + 1) * DX_S + pb] + xv[i * 4 + 1];
                float vg = dx[(m + 2) * DX_S + pb] + xv[i * 4 + 2];
                float vo = dx[(m + 3) * DX_S + pb] + xv[i * 4 + 3];
                float si = 1.0f / (1.0f + expf(-vi));
                float sf = 1.0f / (1.0f + expf(-vf));
                float tg = tanhf(vg);
                float so = 1.0f / (1.0f + expf(-vo));
                float c = sf * (i ? cc1 : cc0) + si * tg;
                if (i) cc1 = c; else cc0 = c;
                float h = so * tanhf(c);
                __nv_bfloat16 hb = __float2bfloat16(h);
                hh_nxt[(pb << 10) + j0 + jj] = hb;
                hl_nxt[(pb << 10) + j0 + jj] =
                    __float2bfloat16(h - __bfloat162float(hb));
                out[((size_t)pb * T_ + t) * H_ + j0 + jj] = h;
            }
        }

        if (t < T_ - 1) grid_barrier();
    }
}

// ---------------------------------------------------------------------------
// Launch: 4 graph nodes
// ---------------------------------------------------------------------------
extern "C" void kernel_launch(void* const* d_in, const int* in_sizes, int n_in,
                              void* d_out, int out_size) {
    const float* x    = (const float*)d_in[0];   // [B, T, D]
    const float* Wx   = (const float*)d_in[1];   // [D, 4H]
    const float* Wh   = (const float*)d_in[2];   // [H, 4H]
    const float* bias = (const float*)d_in[3];   // [4H]
    float* out = (float*)d_out;                  // [B, T, H]

    cudaFuncSetAttribute(lstm_persist,
                         cudaFuncAttributeMaxDynamicSharedMemorySize, SMEM_TOTAL);

    dim3 g1(G4 / 128, M1 / 128);                 // (32, 256)
    gemm_xw<<<g1, 256>>>(x, Wx, bias);
    prep_whT<<<dim3(H_ / 32, G4 / 32), dim3(32, 8)>>>(Wh);
    init_state<<<256, 256>>>();
    lstm_persist<<<NBLK, RTH, SMEM_TOTAL>>>(out);
}

// round 13
// speedup vs baseline: 3.3687x; 1.2969x over previous
#include <cuda_runtime.h>
#include <cuda_bf16.h>
#include <math.h>

typedef unsigned int u32;
typedef unsigned long long u64;

#define B_  64
#define T_  512
#define D_  512
#define H_  1024
#define G4  4096
#define M1  32768          // B_*T_
#define NBLK 128
#define RTH 512

// ---- lstm_persist smem layout (bytes) ----
#define A_STRIDE_B 2064                 // 1032 bf16/row (odd multiple of 16B)
#define SM_AHI 0
#define SM_ALO (32 * A_STRIDE_B)        // 66048
#define SM_B   (2 * 32 * A_STRIDE_B)    // 132096
#define B_STRIDE_B 272                  // 136 bf16/row (odd multiple of 16B)
#define B_LO_OFF 17408                  // 64 * 272
#define BST 34816                       // per chunk buffer (hi + lo)
#define SM_DX (SM_B + 2 * BST)          // 201728
#define DX_S 66
#define SMEM_TOTAL (SM_DX + 2 * 32 * DX_S * 4)   // 218624

// ---- gemm_xw_mma smem layout ----
#define P1_STRIDE 144                   // 64 bf16 = 128B + 16B pad (odd mult of 16B)
#define P1_AHI 0
#define P1_ALO 18432
#define P1_BHI 36864
#define P1_BLO 55296
#define P1_STAGE 73728
#define P1_SMEM (2 * P1_STAGE)          // 147456

// ---------------------------------------------------------------------------
// Device globals (allocation-free scratch)
// ---------------------------------------------------------------------------
__device__ float g_xg[(size_t)M1 * G4];              // xg = x@Wx + b (512 MB)
__device__ __nv_bfloat16 g_xhi[(size_t)M1 * D_];     // x hi  (32 MB)
__device__ __nv_bfloat16 g_xlo[(size_t)M1 * D_];     // x lo
__device__ __nv_bfloat16 g_wxthi[(size_t)G4 * D_];   // Wx^T hi [n][k]
__device__ __nv_bfloat16 g_wxtlo[(size_t)G4 * D_];   // Wx^T lo
__device__ __nv_bfloat16 g_wthi[(size_t)G4 * H_];    // Wh^T hi [m_global][k]
__device__ __nv_bfloat16 g_wtlo[(size_t)G4 * H_];    // Wh^T lo
__device__ __nv_bfloat16 g_hh[2][B_ * H_];           // h hi, [b][k], double-buffered
__device__ __nv_bfloat16 g_hl[2][B_ * H_];           // h lo
__device__ unsigned g_cnt;
__device__ unsigned g_gen;

// ---------------------------------------------------------------------------
// helpers
// ---------------------------------------------------------------------------
__device__ __forceinline__ u32 smem_u32(const void* p) {
    u32 a;
    asm("{ .reg .u64 t; cvta.to.shared.u64 t, %1; cvt.u32.u64 %0, t; }"
        : "=r"(a) : "l"(p));
    return a;
}
__device__ __forceinline__ void ldsm4(u32* r, u32 addr) {
    asm volatile("ldmatrix.sync.aligned.m8n8.x4.shared.b16 {%0,%1,%2,%3}, [%4];"
                 : "=r"(r[0]), "=r"(r[1]), "=r"(r[2]), "=r"(r[3]) : "r"(addr));
}
__device__ __forceinline__ void mma_bf16(float* d, const u32* a, u32 b0, u32 b1) {
    asm volatile(
        "mma.sync.aligned.m16n8k16.row.col.f32.bf16.bf16.f32 "
        "{%0,%1,%2,%3}, {%4,%5,%6,%7}, {%8,%9}, {%0,%1,%2,%3};"
        : "+f"(d[0]), "+f"(d[1]), "+f"(d[2]), "+f"(d[3])
        : "r"(a[0]), "r"(a[1]), "r"(a[2]), "r"(a[3]), "r"(b0), "r"(b1));
}
__device__ __forceinline__ void cpasync16(u32 dst, const void* src) {
    asm volatile("cp.async.cg.shared.global [%0], [%1], 16;" :: "r"(dst), "l"(src));
}

// ---------------------------------------------------------------------------
// prep_x: split x into bf16 hi/lo
// ---------------------------------------------------------------------------
__global__ void prep_x(const float* __restrict__ x) {
    size_t i = (size_t)blockIdx.x * 1024 + threadIdx.x;
    float v = x[i];
    __nv_bfloat16 hi = __float2bfloat16(v);
    g_xhi[i] = hi;
    g_xlo[i] = __float2bfloat16(v - __bfloat162float(hi));
}

// ---------------------------------------------------------------------------
// prep_wxT: Wx[512][4096] -> WxT hi/lo [4096][512]
// ---------------------------------------------------------------------------
__global__ void prep_wxT(const float* __restrict__ Wx) {
    __shared__ float ts[32][33];
    const int k0 = blockIdx.x * 32;
    const int c0 = blockIdx.y * 32;
    const int txl = threadIdx.x, tyl = threadIdx.y;   // (32, 8)
#pragma unroll
    for (int r = 0; r < 4; ++r) {
        int kr = tyl + 8 * r;
        ts[kr][txl] = Wx[(size_t)(k0 + kr) * G4 + c0 + txl];
    }
    __syncthreads();
#pragma unroll
    for (int r = 0; r < 4; ++r) {
        int cl = tyl + 8 * r;
        int c = c0 + cl;
        float w = ts[txl][cl];
        __nv_bfloat16 hi = __float2bfloat16(w);
        g_wxthi[(size_t)c * D_ + k0 + txl] = hi;
        g_wxtlo[(size_t)c * D_ + k0 + txl] =
            __float2bfloat16(w - __bfloat162float(hi));
    }
}

// ---------------------------------------------------------------------------
// prep_whT: Wh -> WhT bf16 hi/lo, gate-interleaved (m = bx*32 + jj*4 + g)
// ---------------------------------------------------------------------------
__global__ void prep_whT(const float* __restrict__ Wh) {
    __shared__ float ts[32][33];
    const int k0 = blockIdx.x * 32;
    const int c0 = blockIdx.y * 32;
    const int txl = threadIdx.x, tyl = threadIdx.y;   // (32, 8)
#pragma unroll
    for (int r = 0; r < 4; ++r) {
        int kr = tyl + 8 * r;
        ts[kr][txl] = Wh[(size_t)(k0 + kr) * G4 + c0 + txl];
    }
    __syncthreads();
#pragma unroll
    for (int r = 0; r < 4; ++r) {
        int cl = tyl + 8 * r;
        int c = c0 + cl;
        int bx = (c & 1023) >> 3;
        int g  = c >> 10;
        int jj = c & 7;
        int mg = bx * 32 + jj * 4 + g;
        float w = ts[txl][cl];
        __nv_bfloat16 hi = __float2bfloat16(w);
        g_wthi[(size_t)mg * H_ + k0 + txl] = hi;
        g_wtlo[(size_t)mg * H_ + k0 + txl] =
            __float2bfloat16(w - __bfloat162float(hi));
    }
}

// ---------------------------------------------------------------------------
// init
// ---------------------------------------------------------------------------
__global__ void init_state() {
    int idx = blockIdx.x * blockDim.x + threadIdx.x;   // 65536
    g_hh[0][idx] = __float2bfloat16(0.0f);
    g_hl[0][idx] = __float2bfloat16(0.0f);
    if (idx == 0) g_cnt = 0u;
}

// ---------------------------------------------------------------------------
// Phase 1 via mma.sync: xg[M1,G4] = x@Wx + bias, bf16 split-3.
// Block 128m x 128n, BK=64, cp.async double-buffered.
// 8 warps: warp tile 32m x 64n.
// ---------------------------------------------------------------------------
__global__ void __launch_bounds__(256, 1)
gemm_xw_mma(const float* __restrict__ bias) {
    extern __shared__ char smc[];
    const u32 sb = smem_u32(smc);
    const int tid = threadIdx.x;
    const int wid = tid >> 5;
    const int lane = tid & 31;
    const int bm = blockIdx.y, bn = blockIdx.x;

    const int wm = (wid >> 1) * 32;
    const int wn = (wid & 1) * 64;

    float acc[2][8][4];
#pragma unroll
    for (int m = 0; m < 2; ++m)
#pragma unroll
        for (int f = 0; f < 8; ++f)
#pragma unroll
            for (int v = 0; v < 4; ++v) acc[m][f][v] = 0.0f;

    const u32 aLane = (u32)((lane & 15) * P1_STRIDE + ((lane >> 4) << 4));
    const u32 bLane = (u32)(((((lane >> 4) << 3) + (lane & 7)) * P1_STRIDE) +
                            (((lane >> 3) & 1) << 4));

    // issue chunk kc into stage s
    auto issue = [&](int kc, int s) {
        const u32 st = sb + (u32)s * P1_STAGE;
#pragma unroll
        for (int it = 0; it < 4; ++it) {
            int cid = tid + it * 256;
            int r = cid >> 3, c = cid & 7;
            u32 doff = (u32)(r * P1_STRIDE + c * 16);
            size_t sia = (((size_t)(bm * 128 + r)) << 9) + kc * 64 + c * 8;
            size_t sib = (((size_t)(bn * 128 + r)) << 9) + kc * 64 + c * 8;
            cpasync16(st + P1_AHI + doff, g_xhi + sia);
            cpasync16(st + P1_ALO + doff, g_xlo + sia);
            cpasync16(st + P1_BHI + doff, g_wxthi + sib);
            cpasync16(st + P1_BLO + doff, g_wxtlo + sib);
        }
        asm volatile("cp.async.commit_group;");
    };

    issue(0, 0);
#pragma unroll 1
    for (int kc = 0; kc < 8; ++kc) {
        if (kc < 7) {
            issue(kc + 1, (kc + 1) & 1);
            asm volatile("cp.async.wait_group 1;");
        } else {
            asm volatile("cp.async.wait_group 0;");
        }
        __syncthreads();
        const u32 st = sb + (u32)(kc & 1) * P1_STAGE;
        const u32 aB = st + P1_AHI + (u32)(wm * P1_STRIDE) + aLane;
        const u32 bB = st + P1_BHI + (u32)(wn * P1_STRIDE) + bLane;
#pragma unroll
        for (int kt = 0; kt < 4; ++kt) {
            const u32 ka = (u32)(kt * 32);
            u32 ah0[4], ah1[4], al0[4], al1[4];
            ldsm4(ah0, aB + ka);
            ldsm4(ah1, aB + 16 * P1_STRIDE + ka);
            ldsm4(al0, aB + (P1_ALO - P1_AHI) + ka);
            ldsm4(al1, aB + (P1_ALO - P1_AHI) + 16 * P1_STRIDE + ka);
#pragma unroll
            for (int s = 0; s < 4; ++s) {
                u32 bh[4], bl[4];
                ldsm4(bh, bB + (u32)(s * 16 * P1_STRIDE) + ka);
                ldsm4(bl, bB + (u32)(s * 16 * P1_STRIDE) + (P1_BLO - P1_BHI) + ka);
                mma_bf16(acc[0][2*s],   ah0, bh[0], bh[1]);
                mma_bf16(acc[0][2*s+1], ah0, bh[2], bh[3]);
                mma_bf16(acc[1][2*s],   ah1, bh[0], bh[1]);
                mma_bf16(acc[1][2*s+1], ah1, bh[2], bh[3]);
                mma_bf16(acc[0][2*s],   al0, bh[0], bh[1]);
                mma_bf16(acc[0][2*s+1], al0, bh[2], bh[3]);
                mma_bf16(acc[1][2*s],   al1, bh[0], bh[1]);
                mma_bf16(acc[1][2*s+1], al1, bh[2], bh[3]);
                mma_bf16(acc[0][2*s],   ah0, bl[0], bl[1]);
                mma_bf16(acc[0][2*s+1], ah0, bl[2], bl[3]);
                mma_bf16(acc[1][2*s],   ah1, bl[0], bl[1]);
                mma_bf16(acc[1][2*s+1], ah1, bl[2], bl[3]);
            }
        }
        __syncthreads();
    }

    // epilogue: bias + store fp32
#pragma unroll
    for (int m = 0; m < 2; ++m) {
        int r0 = bm * 128 + wm + m * 16 + (lane >> 2);
#pragma unroll
        for (int f = 0; f < 8; ++f) {
            int col = bn * 128 + wn + f * 8 + 2 * (lane & 3);
            float b0 = bias[col], b1 = bias[col + 1];
            float* p0 = g_xg + (size_t)r0 * G4 + col;
            float* p1 = p0 + (size_t)8 * G4;
            *(float2*)p0 = make_float2(acc[m][f][0] + b0, acc[m][f][1] + b1);
            *(float2*)p1 = make_float2(acc[m][f][2] + b0, acc[m][f][3] + b1);
        }
    }
}

// ---------------------------------------------------------------------------
// Grid-wide barrier (NBLK blocks resident)
// ---------------------------------------------------------------------------
__device__ __forceinline__ void grid_barrier() {
    __threadfence();
    __syncthreads();
    if (threadIdx.x == 0) {
        volatile unsigned* vg = &g_gen;
        unsigned gen = *vg;
        if (atomicAdd(&g_cnt, 1u) == NBLK - 1) {
            atomicExch(&g_cnt, 0u);
            __threadfence();
            atomicAdd((unsigned*)&g_gen, 1u);
        } else {
            while (*vg == gen) { }
        }
    }
    __syncthreads();
}

// ---------------------------------------------------------------------------
// Persistent mma.sync recurrence. Block bx: M=32 gate-cols (8 hidden x 4
// gates, m=jj*4+g), N=64 batch, K=1024. 16 warps = 8 tiles (16m x 16n) x
// 2 K-sections; chunk pairs staged together so both K-sections compute
// concurrently. WhT hi/lo resident in smem. 3-pass bf16 split, fp32 acc.
// ---------------------------------------------------------------------------
__global__ void __launch_bounds__(RTH, 1)
lstm_persist(float* __restrict__ out) {
    extern __shared__ char smc[];
    const u32 sb = smem_u32(smc);
    const int tid = threadIdx.x;
    const int wid = tid >> 5;
    const int lane = tid & 31;
    const int bx = blockIdx.x;
    const int m0g = bx * 32;
    const int j0 = bx * 8;

    // one-time resident A: WhT hi/lo [32][1024] bf16
#pragma unroll
    for (int it = 0; it < 8; ++it) {
        int cid = tid + it * RTH;            // 0..4095
        int row = cid >> 7, c = cid & 127;
        size_t si = ((size_t)(m0g + row) << 10) + c * 8;
        *(uint4*)(smc + SM_AHI + row * A_STRIDE_B + c * 16) =
            __ldg((const uint4*)(g_wthi + si));
        *(uint4*)(smc + SM_ALO + row * A_STRIDE_B + c * 16) =
            __ldg((const uint4*)(g_wtlo + si));
    }

    const int tile = wid & 7;
    const int ksec = wid >> 3;               // 0 -> even chunks, 1 -> odd
    const int wm = (tile >> 2) * 16;
    const int wn = (tile & 3) * 16;

    const u32 aAddrHi = sb + SM_AHI + (u32)((wm + (lane & 15)) * A_STRIDE_B +
                                            ((lane >> 4) << 4));
    const u32 aAddrLo = aAddrHi + (u32)(SM_ALO - SM_AHI);
    const int bn_row = wn + ((lane >> 4) << 3) + (lane & 7);
    const u32 bbase = sb + SM_B + (u32)ksec * BST +
                      (u32)(bn_row * B_STRIDE_B + (((lane >> 3) & 1) << 4));

    // pointwise: one cell per thread
    const int pb = tid >> 3;                 // batch 0..63
    const int pj = tid & 7;                  // hidden col within block
    float cc = 0.0f;

    __syncthreads();

    for (int t = 0; t < T_; ++t) {
        const __nv_bfloat16* hhi = g_hh[t & 1];
        const __nv_bfloat16* hlo = g_hl[t & 1];
        __nv_bfloat16* hh_nxt = g_hh[(t + 1) & 1];
        __nv_bfloat16* hl_nxt = g_hl[(t + 1) & 1];

        float xv[4];
        {
            const float* xgb = g_xg + ((size_t)pb * T_ + t) * G4 + j0 + pj;
#pragma unroll
            for (int g = 0; g < 4; ++g) xv[g] = __ldcs(xgb + g * H_);
        }

        float acc0[4] = {0.f, 0.f, 0.f, 0.f};
        float acc1[4] = {0.f, 0.f, 0.f, 0.f};

        // stage pair 0 (chunks 0 -> buf0, 1 -> buf1)
#pragma unroll
        for (int q = 0; q < 2; ++q)
#pragma unroll
            for (int it = 0; it < 2; ++it) {
                int cid = tid + it * RTH;
                int row = cid >> 4, c = cid & 15;
                size_t si = ((size_t)row << 10) + q * 128 + c * 8;
                uint4 vh = __ldcg((const uint4*)(hhi + si));
                uint4 vl = __ldcg((const uint4*)(hlo + si));
                char* d = smc + SM_B + q * BST + row * B_STRIDE_B + c * 16;
                *(uint4*)d = vh;
                *(uint4*)(d + B_LO_OFF) = vl;
            }
        __syncthreads();

#pragma unroll 1
        for (int p = 0; p < 4; ++p) {
            uint4 rh[2][2], rl[2][2];
            if (p < 3) {
#pragma unroll
                for (int q = 0; q < 2; ++q)
#pragma unroll
                    for (int it = 0; it < 2; ++it) {
                        int cid = tid + it * RTH;
                        int row = cid >> 4, c = cid & 15;
                        size_t si = ((size_t)row << 10) + (p + 1) * 256 + q * 128 + c * 8;
                        rh[q][it] = __ldcg((const uint4*)(hhi + si));
                        rl[q][it] = __ldcg((const uint4*)(hlo + si));
                    }
            }
            // compute own chunk: kc = 2p + ksec, from buffer `ksec`
            const u32 abase = (u32)((2 * p + ksec) * 256);
#pragma unroll
            for (int kt = 0; kt < 8; ++kt) {
                u32 ahi[4], alo[4], bhi[4], blo[4];
                ldsm4(ahi, aAddrHi + abase + kt * 32);
                ldsm4(alo, aAddrLo + abase + kt * 32);
                ldsm4(bhi, bbase + kt * 32);
                ldsm4(blo, bbase + B_LO_OFF + kt * 32);
                mma_bf16(acc0, ahi, bhi[0], bhi[1]);
                mma_bf16(acc1, ahi, bhi[2], bhi[3]);
                mma_bf16(acc0, alo, bhi[0], bhi[1]);
                mma_bf16(acc1, alo, bhi[2], bhi[3]);
                mma_bf16(acc0, ahi, blo[0], blo[1]);
                mma_bf16(acc1, ahi, blo[2], blo[3]);
            }
            __syncthreads();
            if (p < 3) {
#pragma unroll
                for (int q = 0; q < 2; ++q)
#pragma unroll
                    for (int it = 0; it < 2; ++it) {
                        int cid = tid + it * RTH;
                        int row = cid >> 4, c = cid & 15;
                        char* d = smc + SM_B + q * BST + row * B_STRIDE_B + c * 16;
                        *(uint4*)d = rh[q][it];
                        *(uint4*)(d + B_LO_OFF) = rl[q][it];
                    }
                __syncthreads();
            }
        }

        // write D fragments: Dx[ksec][32][66]
        {
            float* dx = (float*)(smc + SM_DX) + ksec * (32 * DX_S);
            int r0 = wm + (lane >> 2);
            int col = wn + 2 * (lane & 3);
            dx[r0 * DX_S + col]           = acc0[0];
            dx[r0 * DX_S + col + 1]       = acc0[1];
            dx[(r0 + 8) * DX_S + col]     = acc0[2];
            dx[(r0 + 8) * DX_S + col + 1] = acc0[3];
            dx[r0 * DX_S + col + 8]       = acc1[0];
            dx[r0 * DX_S + col + 9]       = acc1[1];
            dx[(r0 + 8) * DX_S + col + 8] = acc1[2];
            dx[(r0 + 8) * DX_S + col + 9] = acc1[3];
        }
        __syncthreads();

        // pointwise: one cell per thread
        {
            const float* dx0 = (const float*)(smc + SM_DX);
            const float* dx1 = dx0 + 32 * DX_S;
            int m = pj << 2;
            float vi = dx0[(m + 0) * DX_S + pb] + dx1[(m + 0) * DX_S + pb] + xv[0];
            float vf = dx0[(m + 1) * DX_S + pb] + dx1[(m + 1) * DX_S + pb] + xv[1];
            float vg = dx0[(m + 2) * DX_S + pb] + dx1[(m + 2) * DX_S + pb] + xv[2];
            float vo = dx0[(m + 3) * DX_S + pb] + dx1[(m + 3) * DX_S + pb] + xv[3];
            float si = 1.0f / (1.0f + expf(-vi));
            float sf = 1.0f / (1.0f + expf(-vf));
            float tg = tanhf(vg);
            float so = 1.0f / (1.0f + expf(-vo));
            float c = sf * cc + si * tg;
            cc = c;
            float h = so * tanhf(c);
            __nv_bfloat16 hb = __float2bfloat16(h);
            hh_nxt[(pb << 10) + j0 + pj] = hb;
            hl_nxt[(pb << 10) + j0 + pj] =
                __float2bfloat16(h - __bfloat162float(hb));
            out[((size_t)pb * T_ + t) * H_ + j0 + pj] = h;
        }

        if (t < T_ - 1) grid_barrier();
    }
}

// ---------------------------------------------------------------------------
// Launch: 6 graph nodes
// ---------------------------------------------------------------------------
extern "C" void kernel_launch(void* const* d_in, const int* in_sizes, int n_in,
                              void* d_out, int out_size) {
    const float* x    = (const float*)d_in[0];   // [B, T, D]
    const float* Wx   = (const float*)d_in[1];   // [D, 4H]
    const float* Wh   = (const float*)d_in[2];   // [H, 4H]
    const float* bias = (const float*)d_in[3];   // [4H]
    float* out = (float*)d_out;                  // [B, T, H]

    cudaFuncSetAttribute(lstm_persist,
                         cudaFuncAttributeMaxDynamicSharedMemorySize, SMEM_TOTAL);
    cudaFuncSetAttribute(gemm_xw_mma,
                         cudaFuncAttributeMaxDynamicSharedMemorySize, P1_SMEM);

    prep_x<<<M1 * D_ / 1024, 1024>>>(x);
    prep_wxT<<<dim3(D_ / 32, G4 / 32), dim3(32, 8)>>>(Wx);
    prep_whT<<<dim3(H_ / 32, G4 / 32), dim3(32, 8)>>>(Wh);
    init_state<<<256, 256>>>();
    gemm_xw_mma<<<dim3(G4 / 128, M1 / 128), 256, P1_SMEM>>>(bias);
    lstm_persist<<<NBLK, RTH, SMEM_TOTAL>>>(out);
}